// round 4
// baseline (speedup 1.0000x reference)
#include <cuda_runtime.h>
#include <cstdint>
#include <math.h>
#include <float.h>

#define BG    128
#define NPG0  512
#define ETOT  524288
#define NTMAX 65536
#define KK1   256
#define KK2   128
#define KK3   64

// ---------------- scratch (device globals) ----------------------------------
__device__ float g_t[(size_t)NTMAX * 128];     // x @ W
__device__ float g_h[(size_t)NTMAX * 128];     // gcn output (post-relu)
__device__ float g_x1[(size_t)BG * KK1 * 128];
__device__ float g_x2[(size_t)BG * KK2 * 128];
__device__ float g_x3[(size_t)BG * KK3 * 128];
__device__ float g_deg[NTMAX];
__device__ float g_dinv[NTMAX];
__device__ float g_score[NTMAX];
__device__ float g_sd[NTMAX];                  // dinv*score (premultiplied)
__device__ float g_sagg[NTMAX];
__device__ int   g_newidx[NTMAX];
__device__ int   g_off[NTMAX + 1];
__device__ int   g_cur[NTMAX];
__device__ int   g_csrc[ETOT];                 // CSR src list bucketed by dst
__device__ int   g_src[ETOT];
__device__ int   g_dst[ETOT];
__device__ float g_emask[ETOT];
__device__ int   g_perm[BG * KK1];
__device__ float g_tanhv[BG * KK1];

// ---------------- helpers ----------------------------------------------------

__device__ __forceinline__ unsigned f2tf32(float x) {
    unsigned r;
    asm("cvt.rna.tf32.f32 %0, %1;" : "=r"(r) : "f"(x));
    return r;
}

__device__ __forceinline__ void mma_tf32(float* d, const unsigned* a, unsigned b0, unsigned b1) {
    asm volatile(
        "mma.sync.aligned.m16n8k8.row.col.f32.tf32.tf32.f32 "
        "{%0,%1,%2,%3},{%4,%5,%6,%7},{%8,%9},{%0,%1,%2,%3};"
        : "+f"(d[0]), "+f"(d[1]), "+f"(d[2]), "+f"(d[3])
        : "r"(a[0]), "r"(a[1]), "r"(a[2]), "r"(a[3]), "r"(b0), "r"(b1));
}

__device__ __forceinline__ void cp_async16(void* sdst, const void* gsrc) {
    unsigned int sa = (unsigned int)__cvta_generic_to_shared(sdst);
    asm volatile("cp.async.cg.shared.global [%0], [%1], 16;" :: "r"(sa), "l"(gsrc));
}

// ---------------- degree / CSR build ----------------------------------------

__global__ void k_fill_deg(int NT) {
    int i = blockIdx.x * blockDim.x + threadIdx.x;
    if (i < NT) g_deg[i] = 1.0f;   // self-loop
}

__global__ void k_deg(const int* __restrict__ dst, const float* __restrict__ emask) {
    int e = blockIdx.x * blockDim.x + threadIdx.x;
    if (e >= ETOT) return;
    float m = emask ? emask[e] : 1.0f;
    if (m != 0.0f) atomicAdd(&g_deg[dst[e]], m);
}

// single block: dinv = rsqrt(deg); exclusive scan of in-degree -> g_off, g_cur
__global__ void k_prep(int NT) {
    __shared__ int ps[1024];
    int tid = threadIdx.x;
    int per = NT >> 10;
    int base = tid * per;
    int sum = 0;
    for (int i = 0; i < per; i++) sum += (int)g_deg[base + i] - 1;
    ps[tid] = sum;
    __syncthreads();
    for (int o = 1; o < 1024; o <<= 1) {
        int v = (tid >= o) ? ps[tid - o] : 0;
        __syncthreads();
        ps[tid] += v;
        __syncthreads();
    }
    int run = ps[tid] - sum;  // exclusive
    for (int i = 0; i < per; i++) {
        float dg = g_deg[base + i];
        g_dinv[base + i] = rsqrtf(dg);
        int c = (int)dg - 1;
        g_off[base + i] = run;
        g_cur[base + i] = run;
        run += c;
    }
    if (tid == 1023) g_off[NT] = run;
}

__global__ void k_csr_fill(const int* __restrict__ src, const int* __restrict__ dst,
                           const float* __restrict__ emask) {
    int e = blockIdx.x * blockDim.x + threadIdx.x;
    if (e >= ETOT) return;
    float m = emask ? emask[e] : 1.0f;
    if (m == 0.0f) return;
    int p = atomicAdd(&g_cur[dst[e]], 1);
    g_csrc[p] = src[e];
}

// ---------------- GEMM: t = X @ W via 3xTF32 mma, 512 thr, 256-row tiles ----

#define WP_STR 136
#define XS_STR 36
#define GEMM_SMEM (128 * WP_STR * 8 + 2 * 256 * XS_STR * 4)

__global__ __launch_bounds__(512, 1)
void k_gemm(const float* __restrict__ X, const float* __restrict__ W) {
    extern __shared__ float sm[];
    float2* Wp = (float2*)sm;                       // [128][WP_STR] (hi,lo)
    float*  Xs = sm + 128 * WP_STR * 2;             // [2][256][XS_STR]
    const int tid = threadIdx.x;
    const size_t R0 = (size_t)blockIdx.x * 256;
    const float* Xg = X + R0 * 128;

    // issue slice 0 loads
    {
        float* xb = Xs;
#pragma unroll
        for (int it = 0; it < 4; it++) {
            int idx = it * 512 + tid;
            int r = idx >> 3, c4 = idx & 7;
            cp_async16(&xb[r * XS_STR + c4 * 4], Xg + (size_t)r * 128 + c4 * 4);
        }
        asm volatile("cp.async.commit_group;");
    }
    // stage W split while slice 0 is in flight
    for (int i = tid; i < 16384; i += 512) {
        int k = i >> 7, n = i & 127;
        float w = W[i];
        unsigned hb = f2tf32(w);
        float hf = __uint_as_float(hb);
        unsigned lb = f2tf32(w - hf);
        Wp[k * WP_STR + n] = make_float2(hf, __uint_as_float(lb));
    }
    asm volatile("cp.async.wait_group 0;");
    __syncthreads();

    const int lane = tid & 31, warp = tid >> 5;
    const int gID = lane >> 2, tg = lane & 3;
    const int wrow = warp * 16;

    float acc[16][4];
#pragma unroll
    for (int j = 0; j < 16; j++)
#pragma unroll
        for (int r = 0; r < 4; r++) acc[j][r] = 0.0f;

#pragma unroll
    for (int s = 0; s < 4; s++) {
        if (s < 3) {
            float* xb = Xs + ((s + 1) & 1) * 256 * XS_STR;
            const float* gb = Xg + (s + 1) * 32;
#pragma unroll
            for (int it = 0; it < 4; it++) {
                int idx = it * 512 + tid;
                int r = idx >> 3, c4 = idx & 7;
                cp_async16(&xb[r * XS_STR + c4 * 4], gb + (size_t)r * 128 + c4 * 4);
            }
            asm volatile("cp.async.commit_group;");
        }
        const float* xb = Xs + (s & 1) * 256 * XS_STR;
#pragma unroll
        for (int kk8 = 0; kk8 < 4; kk8++) {
            const int cb = kk8 * 8;
            const int kb = s * 32 + cb;
            float x0 = xb[(wrow + gID) * XS_STR + cb + tg];
            float x1 = xb[(wrow + 8 + gID) * XS_STR + cb + tg];
            float x2 = xb[(wrow + gID) * XS_STR + cb + 4 + tg];
            float x3 = xb[(wrow + 8 + gID) * XS_STR + cb + 4 + tg];
            unsigned ah[4], al[4];
            ah[0] = f2tf32(x0); al[0] = f2tf32(x0 - __uint_as_float(ah[0]));
            ah[1] = f2tf32(x1); al[1] = f2tf32(x1 - __uint_as_float(ah[1]));
            ah[2] = f2tf32(x2); al[2] = f2tf32(x2 - __uint_as_float(ah[2]));
            ah[3] = f2tf32(x3); al[3] = f2tf32(x3 - __uint_as_float(ah[3]));
#pragma unroll
            for (int j = 0; j < 16; j++) {
                float2 p0 = Wp[(kb + tg) * WP_STR + j * 8 + gID];
                float2 p1 = Wp[(kb + 4 + tg) * WP_STR + j * 8 + gID];
                unsigned b0h = __float_as_uint(p0.x), b0l = __float_as_uint(p0.y);
                unsigned b1h = __float_as_uint(p1.x), b1l = __float_as_uint(p1.y);
                mma_tf32(acc[j], ah, b0h, b1h);
                mma_tf32(acc[j], ah, b0l, b1l);
                mma_tf32(acc[j], al, b0h, b1h);
            }
        }
        if (s < 3) {
            asm volatile("cp.async.wait_group 0;");
            __syncthreads();
        }
    }

    // epilogue: write t directly from fragments (float2, 32B sectors)
    float* t0 = g_t + (R0 + wrow + gID) * 128;
    float* t1 = t0 + 8 * 128;
#pragma unroll
    for (int j = 0; j < 16; j++) {
        int col = j * 8 + tg * 2;
        *(float2*)&t0[col] = make_float2(acc[j][0], acc[j][1]);
        *(float2*)&t1[col] = make_float2(acc[j][2], acc[j][3]);
    }
}

// ---------------- fused gather aggregation + self + relu + score ------------
// one warp per dst node
__global__ void k_gather_agg(const float* __restrict__ bvec, const float* __restrict__ Wsv,
                             int NT) {
    int warp = threadIdx.x >> 5, lane = threadIdx.x & 31;
    int node = blockIdx.x * 8 + warp;
    if (node >= NT) return;
    int beg = g_off[node], end = g_off[node + 1];
    const float4* T = (const float4*)g_t;
    float4 acc = make_float4(0.f, 0.f, 0.f, 0.f);
    for (int j = beg; j < end; j++) {
        int s = g_csrc[j];
        float ns = g_dinv[s];
        float4 tv = T[(size_t)s * 32 + lane];
        acc.x += ns * tv.x; acc.y += ns * tv.y; acc.z += ns * tv.z; acc.w += ns * tv.w;
    }
    float d = g_dinv[node];
    float dd = d * d;
    float4 tn = T[(size_t)node * 32 + lane];
    float4 b4 = ((const float4*)bvec)[lane];
    float4 h;
    h.x = fmaxf(acc.x * d + tn.x * dd + b4.x, 0.f);
    h.y = fmaxf(acc.y * d + tn.y * dd + b4.y, 0.f);
    h.z = fmaxf(acc.z * d + tn.z * dd + b4.z, 0.f);
    h.w = fmaxf(acc.w * d + tn.w * dd + b4.w, 0.f);
    ((float4*)g_h)[(size_t)node * 32 + lane] = h;
    float4 w4 = ((const float4*)Wsv)[lane];
    float v = h.x * w4.x + h.y * w4.y + h.z * w4.z + h.w * w4.w;
#pragma unroll
    for (int o = 16; o; o >>= 1) v += __shfl_xor_sync(0xffffffffu, v, o);
    if (lane == 0) {
        g_score[node] = v;
        g_sd[node] = d * v;
    }
}

// sagg[i] = dinv^2*score[i] + bs + dinv * sum_in(dinv[s]*score[s])
__global__ void k_sagg(const float* __restrict__ bsv, int NT) {
    int i = blockIdx.x * blockDim.x + threadIdx.x;
    if (i >= NT) return;
    int beg = g_off[i], end = g_off[i + 1];
    float sum = 0.f;
    for (int j = beg; j < end; j++) sum += g_sd[g_csrc[j]];
    float d = g_dinv[i];
    g_sagg[i] = d * sum + d * g_sd[i] + bsv[0];
}

// ---------------- top-k / pool / remap --------------------------------------

__global__ void k_topk(int n_pg, int kk) {
    __shared__ float vals[512];
    __shared__ int   idxs[512];
    int g = blockIdx.x, i = threadIdx.x;   // blockDim == n_pg
    int base = g * n_pg;
    vals[i] = -g_sagg[base + i];
    idxs[i] = i;
    g_newidx[base + i] = -1;
    __syncthreads();
    for (int k2 = 2; k2 <= n_pg; k2 <<= 1) {
        for (int j = k2 >> 1; j > 0; j >>= 1) {
            int ixj = i ^ j;
            if (ixj > i) {
                bool up = ((i & k2) == 0);
                float vi = vals[i], vj = vals[ixj];
                bool sw = up ? (vi > vj) : (vi < vj);
                if (sw) {
                    vals[i] = vj; vals[ixj] = vi;
                    int t = idxs[i]; idxs[i] = idxs[ixj]; idxs[ixj] = t;
                }
            }
            __syncthreads();
        }
    }
    if (i < kk) {
        int node = base + idxs[i];
        int nid = g * kk + i;
        g_newidx[node] = nid;
        g_perm[nid] = node;
        g_tanhv[nid] = tanhf(-vals[i]);
    }
}

__global__ void k_pool(float* __restrict__ xout, int kk, float* __restrict__ out, int accFlag) {
    int g = blockIdx.x, c = threadIdx.x;  // 128 threads
    float mx = -FLT_MAX, sm = 0.f;
    for (int j = 0; j < kk; j++) {
        int row = g * kk + j;
        float v = g_h[(size_t)g_perm[row] * 128 + c] * g_tanhv[row];
        xout[(size_t)row * 128 + c] = v;
        mx = fmaxf(mx, v);
        sm += v;
    }
    float mean = sm / (float)kk;
    if (accFlag) {
        out[g * 256 + c]       += mx;
        out[g * 256 + 128 + c] += mean;
    } else {
        out[g * 256 + c]       = mx;
        out[g * 256 + 128 + c] = mean;
    }
}

__global__ void k_remap(const int* __restrict__ src_in, const int* __restrict__ dst_in,
                        const float* __restrict__ emask_in) {
    int e = blockIdx.x * blockDim.x + threadIdx.x;
    if (e >= ETOT) return;
    float m = emask_in ? emask_in[e] : 1.0f;
    int s = src_in[e], d = dst_in[e];
    int ns = g_newidx[s], nd = g_newidx[d];
    bool valid = (ns >= 0) && (nd >= 0);
    g_src[e] = valid ? ns : 0;
    g_dst[e] = valid ? nd : 0;
    g_emask[e] = (valid && m != 0.0f) ? 1.0f : 0.0f;
}

// ---------------- host driver ------------------------------------------------

static void run_stage(const float* xin, int n_pg, int kk,
                      const float* W, const float* bvec, const float* Wsv, const float* bsv,
                      const int* src, const int* dst, const float* emask,
                      float* xout, float* out, int accFlag, int doRemap) {
    int NT = BG * n_pg;
    k_fill_deg<<<NT / 256, 256>>>(NT);
    k_deg<<<ETOT / 256, 256>>>(dst, emask);
    k_prep<<<1, 1024>>>(NT);
    k_csr_fill<<<ETOT / 256, 256>>>(src, dst, emask);
    k_gemm<<<NT / 256, 512, GEMM_SMEM>>>(xin, W);
    k_gather_agg<<<NT / 8, 256>>>(bvec, Wsv, NT);
    k_sagg<<<NT / 256, 256>>>(bsv, NT);
    k_topk<<<BG, n_pg>>>(n_pg, kk);
    k_pool<<<BG, 128>>>(xout, kk, out, accFlag);
    if (doRemap) k_remap<<<ETOT / 256, 256>>>(src, dst, emask);
}

extern "C" void kernel_launch(void* const* d_in, const int* in_sizes, int n_in,
                              void* d_out, int out_size) {
    (void)in_sizes; (void)n_in; (void)out_size;
    const float* x   = (const float*)d_in[0];
    const int*   ei  = (const int*)d_in[1];
    const float* W1  = (const float*)d_in[3];
    const float* b1  = (const float*)d_in[4];
    const float* Ws1 = (const float*)d_in[5];
    const float* bs1 = (const float*)d_in[6];
    const float* W2  = (const float*)d_in[7];
    const float* b2  = (const float*)d_in[8];
    const float* Ws2 = (const float*)d_in[9];
    const float* bs2 = (const float*)d_in[10];
    const float* W3  = (const float*)d_in[11];
    const float* b3  = (const float*)d_in[12];
    const float* Ws3 = (const float*)d_in[13];
    const float* bs3 = (const float*)d_in[14];
    float* out = (float*)d_out;

    static int smem_set = 0;
    if (!smem_set) {
        cudaFuncSetAttribute(k_gemm, cudaFuncAttributeMaxDynamicSharedMemorySize, GEMM_SMEM);
        smem_set = 1;
    }

    float *px1, *px2, *px3;
    int *psrc, *pdst;
    float *pmask;
    cudaGetSymbolAddress((void**)&px1, g_x1);
    cudaGetSymbolAddress((void**)&px2, g_x2);
    cudaGetSymbolAddress((void**)&px3, g_x3);
    cudaGetSymbolAddress((void**)&psrc, g_src);
    cudaGetSymbolAddress((void**)&pdst, g_dst);
    cudaGetSymbolAddress((void**)&pmask, g_emask);

    const int* src0 = ei;
    const int* dst0 = ei + ETOT;

    // Stage 1: N=512 -> K1=256
    run_stage(x, NPG0, KK1, W1, b1, Ws1, bs1, src0, dst0, nullptr, px1, out, 0, 1);
    // Stage 2: K1=256 -> K2=128
    run_stage(px1, KK1, KK2, W2, b2, Ws2, bs2, psrc, pdst, pmask, px2, out, 1, 1);
    // Stage 3: K2=128 -> K3=64
    run_stage(px2, KK2, KK3, W3, b3, Ws3, bs3, psrc, pdst, pmask, px3, out, 1, 0);
}

// round 7
// speedup vs baseline: 1.0091x; 1.0091x over previous
#include <cuda_runtime.h>
#include <cstdint>
#include <math.h>
#include <float.h>

#define BG    128
#define NPG0  512
#define ETOT  524288
#define NTMAX 65536
#define KK1   256
#define KK2   128
#define KK3   64

// ---------------- scratch (device globals) ----------------------------------
__device__ float g_t[(size_t)NTMAX * 128];     // x @ W
__device__ float g_h[(size_t)NTMAX * 128];     // gcn output (post-relu)
__device__ float g_x1[(size_t)BG * KK1 * 128];
__device__ float g_x2[(size_t)BG * KK2 * 128];
__device__ float g_x3[(size_t)BG * KK3 * 128];
__device__ float g_deg[NTMAX];
__device__ float g_dinv[NTMAX];
__device__ float g_sd[NTMAX];                  // dinv*score (premultiplied)
__device__ float g_sagg[NTMAX];
__device__ int   g_newidx[NTMAX];
__device__ int   g_off[NTMAX + 1];
__device__ int   g_cur[NTMAX];
__device__ int   g_csrc[ETOT];                 // CSR src list bucketed by dst
__device__ int   g_src[ETOT];
__device__ int   g_dst[ETOT];
__device__ float g_emask[ETOT];
__device__ int   g_perm[BG * KK1];
__device__ float g_tanhv[BG * KK1];

// ---------------- helpers ----------------------------------------------------

__device__ __forceinline__ unsigned f2tf32(float x) {
    unsigned r;
    asm("cvt.rna.tf32.f32 %0, %1;" : "=r"(r) : "f"(x));
    return r;
}

__device__ __forceinline__ void mma_tf32(float* d, const unsigned* a, unsigned b0, unsigned b1) {
    asm volatile(
        "mma.sync.aligned.m16n8k8.row.col.f32.tf32.tf32.f32 "
        "{%0,%1,%2,%3},{%4,%5,%6,%7},{%8,%9},{%0,%1,%2,%3};"
        : "+f"(d[0]), "+f"(d[1]), "+f"(d[2]), "+f"(d[3])
        : "r"(a[0]), "r"(a[1]), "r"(a[2]), "r"(a[3]), "r"(b0), "r"(b1));
}

__device__ __forceinline__ void cp_async16(void* sdst, const void* gsrc) {
    unsigned int sa = (unsigned int)__cvta_generic_to_shared(sdst);
    asm volatile("cp.async.cg.shared.global [%0], [%1], 16;" :: "r"(sa), "l"(gsrc));
}

// ---------------- degree / CSR build ----------------------------------------

__global__ void k_fill_deg(int NT) {
    int i = blockIdx.x * blockDim.x + threadIdx.x;
    if (i < NT) g_deg[i] = 1.0f;   // self-loop
}

__global__ void k_deg(const int* __restrict__ dst, const float* __restrict__ emask) {
    int e = blockIdx.x * blockDim.x + threadIdx.x;
    if (e >= ETOT) return;
    float m = emask ? emask[e] : 1.0f;
    if (m != 0.0f) atomicAdd(&g_deg[dst[e]], m);
}

// single block: dinv = rsqrt(deg); exclusive scan of in-degree -> g_off, g_cur
__global__ void k_prep(int NT) {
    __shared__ int ps[1024];
    int tid = threadIdx.x;
    int per = NT >> 10;
    int base = tid * per;
    int sum = 0;
    for (int i = 0; i < per; i++) sum += (int)g_deg[base + i] - 1;
    ps[tid] = sum;
    __syncthreads();
    for (int o = 1; o < 1024; o <<= 1) {
        int v = (tid >= o) ? ps[tid - o] : 0;
        __syncthreads();
        ps[tid] += v;
        __syncthreads();
    }
    int run = ps[tid] - sum;  // exclusive
    for (int i = 0; i < per; i++) {
        float dg = g_deg[base + i];
        g_dinv[base + i] = rsqrtf(dg);
        int c = (int)dg - 1;
        g_off[base + i] = run;
        g_cur[base + i] = run;
        run += c;
    }
    if (tid == 1023) g_off[NT] = run;
}

__global__ void k_csr_fill(const int* __restrict__ src, const int* __restrict__ dst,
                           const float* __restrict__ emask) {
    int e = blockIdx.x * blockDim.x + threadIdx.x;
    if (e >= ETOT) return;
    float m = emask ? emask[e] : 1.0f;
    if (m == 0.0f) return;
    int p = atomicAdd(&g_cur[dst[e]], 1);
    g_csrc[p] = src[e];
}

// ---------------- GEMM: t = X @ W via 3xTF32 mma ----------------------------
// CTA: 256 threads (8 warps), tile = 256 rows x 64 cols (blockIdx.y = n-half).
// Warp: 32 rows x 64 cols -> acc[2][8][4].
// smem: W-pair half [128][68] float2 (68KB) + X k=16 slices [2][256][20] (40KB)
// = 108KB -> 2 CTAs/SM, 16 warps/SM.
#define WP_STR 68
#define XS_STR 20
#define GEMM_SMEM (128 * WP_STR * 8 + 2 * 256 * XS_STR * 4)
static_assert(GEMM_SMEM <= 227 * 1024, "smem budget");

__global__ __launch_bounds__(256, 2)
void k_gemm(const float* __restrict__ X, const float* __restrict__ W) {
    extern __shared__ float sm[];
    float2* Wp = (float2*)sm;                       // [128][WP_STR]
    float*  Xs = sm + 128 * WP_STR * 2;             // [2][256][XS_STR]
    const int tid = threadIdx.x;
    const int nh = blockIdx.y;
    const size_t R0 = (size_t)blockIdx.x * 256;
    const float* Xg = X + R0 * 128;

    // issue slice-0 loads (k = 0..15 for all 256 rows)
#pragma unroll
    for (int it = 0; it < 4; it++) {
        int idx = it * 256 + tid;               // 1024 chunks of 16B
        int r = idx >> 2, c4 = idx & 3;
        cp_async16(&Xs[r * XS_STR + c4 * 4], Xg + (size_t)r * 128 + c4 * 4);
    }
    asm volatile("cp.async.commit_group;");

    // stage W column-half, split into tf32 hi/lo pairs
    for (int i = tid; i < 128 * 64; i += 256) {
        int k = i >> 6, n = i & 63;
        float w = W[k * 128 + nh * 64 + n];
        unsigned hb = f2tf32(w);
        float hf = __uint_as_float(hb);
        unsigned lb = f2tf32(w - hf);
        Wp[k * WP_STR + n] = make_float2(hf, __uint_as_float(lb));
    }
    asm volatile("cp.async.wait_group 0;");
    __syncthreads();

    const int lane = tid & 31, warp = tid >> 5;
    const int gID = lane >> 2, tg = lane & 3;
    const int rbase = warp * 32;

    float acc[2][8][4];
#pragma unroll
    for (int mt = 0; mt < 2; mt++)
#pragma unroll
        for (int j = 0; j < 8; j++)
#pragma unroll
            for (int r = 0; r < 4; r++) acc[mt][j][r] = 0.0f;

#pragma unroll
    for (int s = 0; s < 8; s++) {
        if (s < 7) {
            float* xb = Xs + ((s + 1) & 1) * 256 * XS_STR;
            const float* gb = Xg + (s + 1) * 16;
#pragma unroll
            for (int it = 0; it < 4; it++) {
                int idx = it * 256 + tid;
                int r = idx >> 2, c4 = idx & 3;
                cp_async16(&xb[r * XS_STR + c4 * 4], gb + (size_t)r * 128 + c4 * 4);
            }
            asm volatile("cp.async.commit_group;");
        }
        const float* xb = Xs + (s & 1) * 256 * XS_STR;
#pragma unroll
        for (int kk8 = 0; kk8 < 2; kk8++) {
            const int cb = kk8 * 8;               // k within slice
            const int kw = s * 16 + cb;           // k for W rows
            unsigned ah[2][4], al[2][4];
#pragma unroll
            for (int mt = 0; mt < 2; mt++) {
                int rb = rbase + mt * 16;
                float x0 = xb[(rb + gID) * XS_STR + cb + tg];
                float x1 = xb[(rb + 8 + gID) * XS_STR + cb + tg];
                float x2 = xb[(rb + gID) * XS_STR + cb + 4 + tg];
                float x3 = xb[(rb + 8 + gID) * XS_STR + cb + 4 + tg];
                ah[mt][0] = f2tf32(x0); al[mt][0] = f2tf32(x0 - __uint_as_float(ah[mt][0]));
                ah[mt][1] = f2tf32(x1); al[mt][1] = f2tf32(x1 - __uint_as_float(ah[mt][1]));
                ah[mt][2] = f2tf32(x2); al[mt][2] = f2tf32(x2 - __uint_as_float(ah[mt][2]));
                ah[mt][3] = f2tf32(x3); al[mt][3] = f2tf32(x3 - __uint_as_float(ah[mt][3]));
            }
#pragma unroll
            for (int j = 0; j < 8; j++) {
                float2 p0 = Wp[(kw + tg) * WP_STR + j * 8 + gID];
                float2 p1 = Wp[(kw + 4 + tg) * WP_STR + j * 8 + gID];
                unsigned b0h = __float_as_uint(p0.x), b0l = __float_as_uint(p0.y);
                unsigned b1h = __float_as_uint(p1.x), b1l = __float_as_uint(p1.y);
#pragma unroll
                for (int mt = 0; mt < 2; mt++) {
                    mma_tf32(acc[mt][j], ah[mt], b0h, b1h);
                    mma_tf32(acc[mt][j], ah[mt], b0l, b1l);
                    mma_tf32(acc[mt][j], al[mt], b0h, b1h);
                }
            }
        }
        if (s < 7) {
            asm volatile("cp.async.wait_group 0;");
            __syncthreads();
        }
    }

    // epilogue: direct float2 stores
#pragma unroll
    for (int mt = 0; mt < 2; mt++) {
        float* t0 = g_t + (R0 + rbase + mt * 16 + gID) * 128 + nh * 64;
        float* t1 = t0 + 8 * 128;
#pragma unroll
        for (int j = 0; j < 8; j++) {
            int col = j * 8 + tg * 2;
            *(float2*)&t0[col] = make_float2(acc[mt][j][0], acc[mt][j][1]);
            *(float2*)&t1[col] = make_float2(acc[mt][j][2], acc[mt][j][3]);
        }
    }
}

// ---------------- fused gather aggregation + self + relu + score ------------
// one warp per dst node
__global__ void k_gather_agg(const float* __restrict__ bvec, const float* __restrict__ Wsv,
                             int NT) {
    int warp = threadIdx.x >> 5, lane = threadIdx.x & 31;
    int node = blockIdx.x * 8 + warp;
    if (node >= NT) return;
    int beg = g_off[node], end = g_off[node + 1];
    const float4* T = (const float4*)g_t;
    float4 acc = make_float4(0.f, 0.f, 0.f, 0.f);
    for (int j = beg; j < end; j++) {
        int s = g_csrc[j];
        float ns = g_dinv[s];
        float4 tv = T[(size_t)s * 32 + lane];
        acc.x += ns * tv.x; acc.y += ns * tv.y; acc.z += ns * tv.z; acc.w += ns * tv.w;
    }
    float d = g_dinv[node];
    float dd = d * d;
    float4 tn = T[(size_t)node * 32 + lane];
    float4 b4 = ((const float4*)bvec)[lane];
    float4 h;
    h.x = fmaxf(acc.x * d + tn.x * dd + b4.x, 0.f);
    h.y = fmaxf(acc.y * d + tn.y * dd + b4.y, 0.f);
    h.z = fmaxf(acc.z * d + tn.z * dd + b4.z, 0.f);
    h.w = fmaxf(acc.w * d + tn.w * dd + b4.w, 0.f);
    ((float4*)g_h)[(size_t)node * 32 + lane] = h;
    float4 w4 = ((const float4*)Wsv)[lane];
    float v = h.x * w4.x + h.y * w4.y + h.z * w4.z + h.w * w4.w;
#pragma unroll
    for (int o = 16; o; o >>= 1) v += __shfl_xor_sync(0xffffffffu, v, o);
    if (lane == 0) g_sd[node] = d * v;
}

// sagg[i] = dinv*sd[i] + bs + dinv * sum_in(sd[s])   where sd = dinv*score
__global__ void k_sagg(const float* __restrict__ bsv, int NT) {
    int i = blockIdx.x * blockDim.x + threadIdx.x;
    if (i >= NT) return;
    int beg = g_off[i], end = g_off[i + 1];
    float sum = 0.f;
    for (int j = beg; j < end; j++) sum += g_sd[g_csrc[j]];
    float d = g_dinv[i];
    g_sagg[i] = d * sum + d * g_sd[i] + bsv[0];
}

// ---------------- top-k / pool / remap --------------------------------------

__global__ void k_topk(int n_pg, int kk) {
    __shared__ float vals[512];
    __shared__ int   idxs[512];
    int g = blockIdx.x, i = threadIdx.x;   // blockDim == n_pg
    int base = g * n_pg;
    vals[i] = -g_sagg[base + i];
    idxs[i] = i;
    g_newidx[base + i] = -1;
    __syncthreads();
    for (int k2 = 2; k2 <= n_pg; k2 <<= 1) {
        for (int j = k2 >> 1; j > 0; j >>= 1) {
            int ixj = i ^ j;
            if (ixj > i) {
                bool up = ((i & k2) == 0);
                float vi = vals[i], vj = vals[ixj];
                bool sw = up ? (vi > vj) : (vi < vj);
                if (sw) {
                    vals[i] = vj; vals[ixj] = vi;
                    int t = idxs[i]; idxs[i] = idxs[ixj]; idxs[ixj] = t;
                }
            }
            __syncthreads();
        }
    }
    if (i < kk) {
        int node = base + idxs[i];
        int nid = g * kk + i;
        g_newidx[node] = nid;
        g_perm[nid] = node;
        g_tanhv[nid] = tanhf(-vals[i]);
    }
}

__global__ void k_pool(float* __restrict__ xout, int kk, float* __restrict__ out, int accFlag) {
    int g = blockIdx.x, c = threadIdx.x;  // 128 threads
    float mx = -FLT_MAX, sm = 0.f;
    for (int j = 0; j < kk; j++) {
        int row = g * kk + j;
        float v = g_h[(size_t)g_perm[row] * 128 + c] * g_tanhv[row];
        xout[(size_t)row * 128 + c] = v;
        mx = fmaxf(mx, v);
        sm += v;
    }
    float mean = sm / (float)kk;
    if (accFlag) {
        out[g * 256 + c]       += mx;
        out[g * 256 + 128 + c] += mean;
    } else {
        out[g * 256 + c]       = mx;
        out[g * 256 + 128 + c] = mean;
    }
}

__global__ void k_remap(const int* __restrict__ src_in, const int* __restrict__ dst_in,
                        const float* __restrict__ emask_in) {
    int e = blockIdx.x * blockDim.x + threadIdx.x;
    if (e >= ETOT) return;
    float m = emask_in ? emask_in[e] : 1.0f;
    int s = src_in[e], d = dst_in[e];
    int ns = g_newidx[s], nd = g_newidx[d];
    bool valid = (ns >= 0) && (nd >= 0);
    g_src[e] = valid ? ns : 0;
    g_dst[e] = valid ? nd : 0;
    g_emask[e] = (valid && m != 0.0f) ? 1.0f : 0.0f;
}

// ---------------- host driver ------------------------------------------------

static void run_stage(const float* xin, int n_pg, int kk,
                      const float* W, const float* bvec, const float* Wsv, const float* bsv,
                      const int* src, const int* dst, const float* emask,
                      float* xout, float* out, int accFlag, int doRemap) {
    int NT = BG * n_pg;
    k_fill_deg<<<NT / 256, 256>>>(NT);
    k_deg<<<ETOT / 256, 256>>>(dst, emask);
    k_prep<<<1, 1024>>>(NT);
    k_csr_fill<<<ETOT / 256, 256>>>(src, dst, emask);
    dim3 ggrid(NT / 256, 2);
    k_gemm<<<ggrid, 256, GEMM_SMEM>>>(xin, W);
    k_gather_agg<<<NT / 8, 256>>>(bvec, Wsv, NT);
    k_sagg<<<NT / 256, 256>>>(bsv, NT);
    k_topk<<<BG, n_pg>>>(n_pg, kk);
    k_pool<<<BG, 128>>>(xout, kk, out, accFlag);
    if (doRemap) k_remap<<<ETOT / 256, 256>>>(src, dst, emask);
}

extern "C" void kernel_launch(void* const* d_in, const int* in_sizes, int n_in,
                              void* d_out, int out_size) {
    (void)in_sizes; (void)n_in; (void)out_size;
    const float* x   = (const float*)d_in[0];
    const int*   ei  = (const int*)d_in[1];
    const float* W1  = (const float*)d_in[3];
    const float* b1  = (const float*)d_in[4];
    const float* Ws1 = (const float*)d_in[5];
    const float* bs1 = (const float*)d_in[6];
    const float* W2  = (const float*)d_in[7];
    const float* b2  = (const float*)d_in[8];
    const float* Ws2 = (const float*)d_in[9];
    const float* bs2 = (const float*)d_in[10];
    const float* W3  = (const float*)d_in[11];
    const float* b3  = (const float*)d_in[12];
    const float* Ws3 = (const float*)d_in[13];
    const float* bs3 = (const float*)d_in[14];
    float* out = (float*)d_out;

    static int smem_set = 0;
    if (!smem_set) {
        cudaFuncSetAttribute(k_gemm, cudaFuncAttributeMaxDynamicSharedMemorySize, GEMM_SMEM);
        smem_set = 1;
    }

    float *px1, *px2, *px3;
    int *psrc, *pdst;
    float *pmask;
    cudaGetSymbolAddress((void**)&px1, g_x1);
    cudaGetSymbolAddress((void**)&px2, g_x2);
    cudaGetSymbolAddress((void**)&px3, g_x3);
    cudaGetSymbolAddress((void**)&psrc, g_src);
    cudaGetSymbolAddress((void**)&pdst, g_dst);
    cudaGetSymbolAddress((void**)&pmask, g_emask);

    const int* src0 = ei;
    const int* dst0 = ei + ETOT;

    // Stage 1: N=512 -> K1=256
    run_stage(x, NPG0, KK1, W1, b1, Ws1, bs1, src0, dst0, nullptr, px1, out, 0, 1);
    // Stage 2: K1=256 -> K2=128
    run_stage(px1, KK1, KK2, W2, b2, Ws2, bs2, psrc, pdst, pmask, px2, out, 1, 1);
    // Stage 3: K2=128 -> K3=64
    run_stage(px2, KK2, KK3, W3, b3, Ws3, bs3, psrc, pdst, pmask, px3, out, 1, 0);
}

// round 9
// speedup vs baseline: 1.9865x; 1.9685x over previous
#include <cuda_runtime.h>
#include <cstdint>
#include <math.h>
#include <float.h>

#define BG    128
#define NPG0  512
#define ETOT  524288
#define NTMAX 65536
#define KK1   256
#define KK2   128
#define KK3   64

// ---------------- scratch (device globals) ----------------------------------
__device__ float g_t[(size_t)NTMAX * 128];     // x @ W
__device__ float g_h[(size_t)NTMAX * 128];     // gcn output (post-relu)
__device__ float g_x1[(size_t)BG * KK1 * 128];
__device__ float g_x2[(size_t)BG * KK2 * 128];
__device__ float g_x3[(size_t)BG * KK3 * 128];
__device__ float g_deg[NTMAX];
__device__ float g_dinv[NTMAX];
__device__ float g_sd[NTMAX];                  // dinv*score (premultiplied)
__device__ float g_sagg[NTMAX];
__device__ int   g_newidx[NTMAX];
__device__ int   g_off[NTMAX + 4];
__device__ int   g_cur[NTMAX];
__device__ int   g_toff[NTMAX / 4];            // per-thread (4-elem chunk) prefix
__device__ int   g_bsum[64];                   // per-block in-degree sums
__device__ int   g_csrc[ETOT];                 // CSR src list bucketed by dst
__device__ int   g_src[ETOT];
__device__ int   g_dst[ETOT];
__device__ float g_emask[ETOT];
__device__ int   g_perm[BG * KK1];
__device__ float g_tanhv[BG * KK1];

// ---------------- helpers ----------------------------------------------------

__device__ __forceinline__ unsigned f2tf32(float x) {
    unsigned r;
    asm("cvt.rna.tf32.f32 %0, %1;" : "=r"(r) : "f"(x));
    return r;
}

__device__ __forceinline__ void mma_tf32(float* d, const unsigned* a, unsigned b0, unsigned b1) {
    asm volatile(
        "mma.sync.aligned.m16n8k8.row.col.f32.tf32.tf32.f32 "
        "{%0,%1,%2,%3},{%4,%5,%6,%7},{%8,%9},{%0,%1,%2,%3};"
        : "+f"(d[0]), "+f"(d[1]), "+f"(d[2]), "+f"(d[3])
        : "r"(a[0]), "r"(a[1]), "r"(a[2]), "r"(a[3]), "r"(b0), "r"(b1));
}

__device__ __forceinline__ void cp_async16(void* sdst, const void* gsrc) {
    unsigned int sa = (unsigned int)__cvta_generic_to_shared(sdst);
    asm volatile("cp.async.cg.shared.global [%0], [%1], 16;" :: "r"(sa), "l"(gsrc));
}

// ---------------- degree -----------------------------------------------------

__global__ void k_fill_deg(int NT) {
    int i = blockIdx.x * blockDim.x + threadIdx.x;
    if (i < NT) g_deg[i] = 1.0f;   // self-loop
}

__global__ void k_deg(const int* __restrict__ dst, const float* __restrict__ emask) {
    int e = blockIdx.x * blockDim.x + threadIdx.x;
    if (e >= ETOT) return;
    float m = emask ? emask[e] : 1.0f;
    if (m != 0.0f) atomicAdd(&g_deg[dst[e]], m);
}

// ---------------- coalesced 3-phase in-degree scan ---------------------------
// phase 1: dinv + per-thread (4 elems) exclusive prefix within block + block sum
__global__ void k_scan1(int NT) {
    __shared__ int wsum[8];
    int tid = threadIdx.x, blk = blockIdx.x;
    int base = blk * 1024 + tid * 4;
    float4 dg = *(const float4*)&g_deg[base];
    float4 di = make_float4(rsqrtf(dg.x), rsqrtf(dg.y), rsqrtf(dg.z), rsqrtf(dg.w));
    *(float4*)&g_dinv[base] = di;
    int c = (int)(dg.x + dg.y + dg.z + dg.w) - 4;   // in-degree of the 4 nodes
    int lane = tid & 31, wid = tid >> 5;
    // warp inclusive scan
    int v = c;
#pragma unroll
    for (int o = 1; o < 32; o <<= 1) {
        int u = __shfl_up_sync(0xffffffffu, v, o);
        if (lane >= o) v += u;
    }
    int excl = v - c;                 // exclusive within warp
    if (lane == 31) wsum[wid] = v;    // warp total
    __syncthreads();
    if (tid == 0) {                   // exclusive scan of 8 warp totals
        int run = 0;
#pragma unroll
        for (int i = 0; i < 8; i++) { int t = wsum[i]; wsum[i] = run; run += t; }
    }
    __syncthreads();
    int thread_excl = excl + wsum[wid];   // exclusive within block
    g_toff[blk * 256 + tid] = thread_excl;
    if (tid == 255) g_bsum[blk] = thread_excl + c;   // block total
}

// phase 2: exclusive scan of block sums (nblk <= 64) + total -> g_off[NT]
__global__ void k_scan2(int nblk, int NT) {
    if (threadIdx.x == 0) {
        int run = 0;
        for (int i = 0; i < nblk; i++) {
            int b = g_bsum[i];
            g_bsum[i] = run;
            run += b;
        }
        g_off[NT] = run;
    }
}

// phase 3: per-element offsets, int4-coalesced
__global__ void k_scan3(int NT) {
    int tid = threadIdx.x, blk = blockIdx.x;
    int base = blk * 1024 + tid * 4;
    float4 dg = *(const float4*)&g_deg[base];
    int run = g_toff[blk * 256 + tid] + g_bsum[blk];
    int4 off;
    off.x = run; run += (int)dg.x - 1;
    off.y = run; run += (int)dg.y - 1;
    off.z = run; run += (int)dg.z - 1;
    off.w = run; run += (int)dg.w - 1;
    *(int4*)&g_off[base] = off;
    *(int4*)&g_cur[base] = off;
}

__global__ void k_csr_fill(const int* __restrict__ src, const int* __restrict__ dst,
                           const float* __restrict__ emask) {
    int e = blockIdx.x * blockDim.x + threadIdx.x;
    if (e >= ETOT) return;
    float m = emask ? emask[e] : 1.0f;
    if (m == 0.0f) return;
    int p = atomicAdd(&g_cur[dst[e]], 1);
    g_csrc[p] = src[e];
}

// ---------------- GEMM: t = X @ W via 3xTF32 mma ----------------------------
#define WP_STR 68
#define XS_STR 20
#define GEMM_SMEM (128 * WP_STR * 8 + 2 * 256 * XS_STR * 4)
static_assert(GEMM_SMEM <= 227 * 1024, "smem budget");

__global__ __launch_bounds__(256, 2)
void k_gemm(const float* __restrict__ X, const float* __restrict__ W) {
    extern __shared__ float sm[];
    float2* Wp = (float2*)sm;                       // [128][WP_STR]
    float*  Xs = sm + 128 * WP_STR * 2;             // [2][256][XS_STR]
    const int tid = threadIdx.x;
    const int nh = blockIdx.y;
    const size_t R0 = (size_t)blockIdx.x * 256;
    const float* Xg = X + R0 * 128;

#pragma unroll
    for (int it = 0; it < 4; it++) {
        int idx = it * 256 + tid;
        int r = idx >> 2, c4 = idx & 3;
        cp_async16(&Xs[r * XS_STR + c4 * 4], Xg + (size_t)r * 128 + c4 * 4);
    }
    asm volatile("cp.async.commit_group;");

    for (int i = tid; i < 128 * 64; i += 256) {
        int k = i >> 6, n = i & 63;
        float w = W[k * 128 + nh * 64 + n];
        unsigned hb = f2tf32(w);
        float hf = __uint_as_float(hb);
        unsigned lb = f2tf32(w - hf);
        Wp[k * WP_STR + n] = make_float2(hf, __uint_as_float(lb));
    }
    asm volatile("cp.async.wait_group 0;");
    __syncthreads();

    const int lane = tid & 31, warp = tid >> 5;
    const int gID = lane >> 2, tg = lane & 3;
    const int rbase = warp * 32;

    float acc[2][8][4];
#pragma unroll
    for (int mt = 0; mt < 2; mt++)
#pragma unroll
        for (int j = 0; j < 8; j++)
#pragma unroll
            for (int r = 0; r < 4; r++) acc[mt][j][r] = 0.0f;

#pragma unroll
    for (int s = 0; s < 8; s++) {
        if (s < 7) {
            float* xb = Xs + ((s + 1) & 1) * 256 * XS_STR;
            const float* gb = Xg + (s + 1) * 16;
#pragma unroll
            for (int it = 0; it < 4; it++) {
                int idx = it * 256 + tid;
                int r = idx >> 2, c4 = idx & 3;
                cp_async16(&xb[r * XS_STR + c4 * 4], gb + (size_t)r * 128 + c4 * 4);
            }
            asm volatile("cp.async.commit_group;");
        }
        const float* xb = Xs + (s & 1) * 256 * XS_STR;
#pragma unroll
        for (int kk8 = 0; kk8 < 2; kk8++) {
            const int cb = kk8 * 8;
            const int kw = s * 16 + cb;
            unsigned ah[2][4], al[2][4];
#pragma unroll
            for (int mt = 0; mt < 2; mt++) {
                int rb = rbase + mt * 16;
                float x0 = xb[(rb + gID) * XS_STR + cb + tg];
                float x1 = xb[(rb + 8 + gID) * XS_STR + cb + tg];
                float x2 = xb[(rb + gID) * XS_STR + cb + 4 + tg];
                float x3 = xb[(rb + 8 + gID) * XS_STR + cb + 4 + tg];
                ah[mt][0] = f2tf32(x0); al[mt][0] = f2tf32(x0 - __uint_as_float(ah[mt][0]));
                ah[mt][1] = f2tf32(x1); al[mt][1] = f2tf32(x1 - __uint_as_float(ah[mt][1]));
                ah[mt][2] = f2tf32(x2); al[mt][2] = f2tf32(x2 - __uint_as_float(ah[mt][2]));
                ah[mt][3] = f2tf32(x3); al[mt][3] = f2tf32(x3 - __uint_as_float(ah[mt][3]));
            }
#pragma unroll
            for (int j = 0; j < 8; j++) {
                float2 p0 = Wp[(kw + tg) * WP_STR + j * 8 + gID];
                float2 p1 = Wp[(kw + 4 + tg) * WP_STR + j * 8 + gID];
                unsigned b0h = __float_as_uint(p0.x), b0l = __float_as_uint(p0.y);
                unsigned b1h = __float_as_uint(p1.x), b1l = __float_as_uint(p1.y);
#pragma unroll
                for (int mt = 0; mt < 2; mt++) {
                    mma_tf32(acc[mt][j], ah[mt], b0h, b1h);
                    mma_tf32(acc[mt][j], ah[mt], b0l, b1l);
                    mma_tf32(acc[mt][j], al[mt], b0h, b1h);
                }
            }
        }
        if (s < 7) {
            asm volatile("cp.async.wait_group 0;");
            __syncthreads();
        }
    }

#pragma unroll
    for (int mt = 0; mt < 2; mt++) {
        float* t0 = g_t + (R0 + rbase + mt * 16 + gID) * 128 + nh * 64;
        float* t1 = t0 + 8 * 128;
#pragma unroll
        for (int j = 0; j < 8; j++) {
            int col = j * 8 + tg * 2;
            *(float2*)&t0[col] = make_float2(acc[mt][j][0], acc[mt][j][1]);
            *(float2*)&t1[col] = make_float2(acc[mt][j][2], acc[mt][j][3]);
        }
    }
}

// ---------------- fused gather aggregation + self + relu + score ------------
// one warp per dst node; neighbor indices loaded lane-parallel then shfl-bcast
__global__ void k_gather_agg(const float* __restrict__ bvec, const float* __restrict__ Wsv,
                             int NT) {
    int warp = threadIdx.x >> 5, lane = threadIdx.x & 31;
    int node = blockIdx.x * 8 + warp;
    if (node >= NT) return;
    int beg = g_off[node], end = g_off[node + 1];
    int cnt = end - beg;
    const float4* T = (const float4*)g_t;
    float4 acc = make_float4(0.f, 0.f, 0.f, 0.f);
    for (int j0 = 0; j0 < cnt; j0 += 32) {
        int n = cnt - j0; if (n > 32) n = 32;
        int sj = 0; float nsj = 0.f;
        if (lane < n) {
            sj = g_csrc[beg + j0 + lane];
            nsj = g_dinv[sj];
        }
        for (int j = 0; j < n; j++) {
            int s = __shfl_sync(0xffffffffu, sj, j);
            float ns = __shfl_sync(0xffffffffu, nsj, j);
            float4 tv = T[(size_t)s * 32 + lane];
            acc.x += ns * tv.x; acc.y += ns * tv.y; acc.z += ns * tv.z; acc.w += ns * tv.w;
        }
    }
    float d = g_dinv[node];
    float dd = d * d;
    float4 tn = T[(size_t)node * 32 + lane];
    float4 b4 = ((const float4*)bvec)[lane];
    float4 h;
    h.x = fmaxf(acc.x * d + tn.x * dd + b4.x, 0.f);
    h.y = fmaxf(acc.y * d + tn.y * dd + b4.y, 0.f);
    h.z = fmaxf(acc.z * d + tn.z * dd + b4.z, 0.f);
    h.w = fmaxf(acc.w * d + tn.w * dd + b4.w, 0.f);
    ((float4*)g_h)[(size_t)node * 32 + lane] = h;
    float4 w4 = ((const float4*)Wsv)[lane];
    float v = h.x * w4.x + h.y * w4.y + h.z * w4.z + h.w * w4.w;
#pragma unroll
    for (int o = 16; o; o >>= 1) v += __shfl_xor_sync(0xffffffffu, v, o);
    if (lane == 0) g_sd[node] = d * v;
}

// sagg[i] = dinv*sd[i] + bs + dinv * sum_in(sd[s])
__global__ void k_sagg(const float* __restrict__ bsv, int NT) {
    int i = blockIdx.x * blockDim.x + threadIdx.x;
    if (i >= NT) return;
    int beg = g_off[i], end = g_off[i + 1];
    float sum = 0.f;
    for (int j = beg; j < end; j++) sum += g_sd[g_csrc[j]];
    float d = g_dinv[i];
    g_sagg[i] = d * sum + d * g_sd[i] + bsv[0];
}

// ---------------- top-k / pool / remap --------------------------------------

__global__ void k_topk(int n_pg, int kk) {
    __shared__ float vals[512];
    __shared__ int   idxs[512];
    int g = blockIdx.x, i = threadIdx.x;
    int base = g * n_pg;
    vals[i] = -g_sagg[base + i];
    idxs[i] = i;
    g_newidx[base + i] = -1;
    __syncthreads();
    for (int k2 = 2; k2 <= n_pg; k2 <<= 1) {
        for (int j = k2 >> 1; j > 0; j >>= 1) {
            int ixj = i ^ j;
            if (ixj > i) {
                bool up = ((i & k2) == 0);
                float vi = vals[i], vj = vals[ixj];
                bool sw = up ? (vi > vj) : (vi < vj);
                if (sw) {
                    vals[i] = vj; vals[ixj] = vi;
                    int t = idxs[i]; idxs[i] = idxs[ixj]; idxs[ixj] = t;
                }
            }
            __syncthreads();
        }
    }
    if (i < kk) {
        int node = base + idxs[i];
        int nid = g * kk + i;
        g_newidx[node] = nid;
        g_perm[nid] = node;
        g_tanhv[nid] = tanhf(-vals[i]);
    }
}

__global__ void k_pool(float* __restrict__ xout, int kk, float* __restrict__ out, int accFlag) {
    int g = blockIdx.x, c = threadIdx.x;
    float mx = -FLT_MAX, sm = 0.f;
    for (int j = 0; j < kk; j++) {
        int row = g * kk + j;
        float v = g_h[(size_t)g_perm[row] * 128 + c] * g_tanhv[row];
        xout[(size_t)row * 128 + c] = v;
        mx = fmaxf(mx, v);
        sm += v;
    }
    float mean = sm / (float)kk;
    if (accFlag) {
        out[g * 256 + c]       += mx;
        out[g * 256 + 128 + c] += mean;
    } else {
        out[g * 256 + c]       = mx;
        out[g * 256 + 128 + c] = mean;
    }
}

__global__ void k_remap(const int* __restrict__ src_in, const int* __restrict__ dst_in,
                        const float* __restrict__ emask_in) {
    int e = blockIdx.x * blockDim.x + threadIdx.x;
    if (e >= ETOT) return;
    float m = emask_in ? emask_in[e] : 1.0f;
    int s = src_in[e], d = dst_in[e];
    int ns = g_newidx[s], nd = g_newidx[d];
    bool valid = (ns >= 0) && (nd >= 0);
    g_src[e] = valid ? ns : 0;
    g_dst[e] = valid ? nd : 0;
    g_emask[e] = (valid && m != 0.0f) ? 1.0f : 0.0f;
}

// ---------------- host driver ------------------------------------------------

static void run_stage(const float* xin, int n_pg, int kk,
                      const float* W, const float* bvec, const float* Wsv, const float* bsv,
                      const int* src, const int* dst, const float* emask,
                      float* xout, float* out, int accFlag, int doRemap) {
    int NT = BG * n_pg;
    int nblk = NT / 1024;
    k_fill_deg<<<NT / 256, 256>>>(NT);
    k_deg<<<ETOT / 256, 256>>>(dst, emask);
    k_scan1<<<nblk, 256>>>(NT);
    k_scan2<<<1, 32>>>(nblk, NT);
    k_scan3<<<nblk, 256>>>(NT);
    k_csr_fill<<<ETOT / 256, 256>>>(src, dst, emask);
    dim3 ggrid(NT / 256, 2);
    k_gemm<<<ggrid, 256, GEMM_SMEM>>>(xin, W);
    k_gather_agg<<<NT / 8, 256>>>(bvec, Wsv, NT);
    k_sagg<<<NT / 256, 256>>>(bsv, NT);
    k_topk<<<BG, n_pg>>>(n_pg, kk);
    k_pool<<<BG, 128>>>(xout, kk, out, accFlag);
    if (doRemap) k_remap<<<ETOT / 256, 256>>>(src, dst, emask);
}

extern "C" void kernel_launch(void* const* d_in, const int* in_sizes, int n_in,
                              void* d_out, int out_size) {
    (void)in_sizes; (void)n_in; (void)out_size;
    const float* x   = (const float*)d_in[0];
    const int*   ei  = (const int*)d_in[1];
    const float* W1  = (const float*)d_in[3];
    const float* b1  = (const float*)d_in[4];
    const float* Ws1 = (const float*)d_in[5];
    const float* bs1 = (const float*)d_in[6];
    const float* W2  = (const float*)d_in[7];
    const float* b2  = (const float*)d_in[8];
    const float* Ws2 = (const float*)d_in[9];
    const float* bs2 = (const float*)d_in[10];
    const float* W3  = (const float*)d_in[11];
    const float* b3  = (const float*)d_in[12];
    const float* Ws3 = (const float*)d_in[13];
    const float* bs3 = (const float*)d_in[14];
    float* out = (float*)d_out;

    static int smem_set = 0;
    if (!smem_set) {
        cudaFuncSetAttribute(k_gemm, cudaFuncAttributeMaxDynamicSharedMemorySize, GEMM_SMEM);
        smem_set = 1;
    }

    float *px1, *px2, *px3;
    int *psrc, *pdst;
    float *pmask;
    cudaGetSymbolAddress((void**)&px1, g_x1);
    cudaGetSymbolAddress((void**)&px2, g_x2);
    cudaGetSymbolAddress((void**)&px3, g_x3);
    cudaGetSymbolAddress((void**)&psrc, g_src);
    cudaGetSymbolAddress((void**)&pdst, g_dst);
    cudaGetSymbolAddress((void**)&pmask, g_emask);

    const int* src0 = ei;
    const int* dst0 = ei + ETOT;

    // Stage 1: N=512 -> K1=256
    run_stage(x, NPG0, KK1, W1, b1, Ws1, bs1, src0, dst0, nullptr, px1, out, 0, 1);
    // Stage 2: K1=256 -> K2=128
    run_stage(px1, KK1, KK2, W2, b2, Ws2, bs2, psrc, pdst, pmask, px2, out, 1, 1);
    // Stage 3: K2=128 -> K3=64
    run_stage(px2, KK2, KK3, W3, b3, Ws3, bs3, psrc, pdst, pmask, px3, out, 1, 0);
}